// round 16
// baseline (speedup 1.0000x reference)
#include <cuda_runtime.h>

// y = min(((x + 1) * 0.75)^2, 10)  — elementwise over 8192*8192 fp32.
// FINAL — best-measured configuration (R15: wall 81.98us, ncu 74.7us,
// DRAM 81.3%, ~6.44 TB/s). HBM-bound at the sustained power-limited
// roofline: 512MB irreducible traffic / ~6.45 TB/s ≈ 80us floor.
//
// Complete isolated lever sweep (15 rounds):
//  - per-thread MLP: saturates at 4 front-batched float4 loads
//    (the only real win: DRAM 77.8% -> 82%); MLP=8 regresses occupancy
//  - block size 256/512/1024: statistical tie (1024 = best wall sample)
//  - 128-bit vs 256-bit (v8.f32) accesses: tie
//  - cache hints (__ldcs/__stcs): neutral (de-confounded)
//  - persistent grid / interleaved ld-st batches: regress
//  - coalesced blockDim-stride addressing, exact grid, no bounds checks:
//    67108864 = 4096 blocks * 1024 thr * 16 elems

#define T 1024u

__device__ __forceinline__ float f(float x) {
    float t = (x + 1.0f) * 0.75f;
    float y = t * t;
    return fminf(y, 10.0f);
}

__device__ __forceinline__ float4 f4(float4 v) {
    float4 r;
    r.x = f(v.x); r.y = f(v.y); r.z = f(v.z); r.w = f(v.w);
    return r;
}

__global__ __launch_bounds__(1024) void elemwise_kernel(const float4* __restrict__ in,
                                                        float4* __restrict__ out) {
    unsigned base = blockIdx.x * (T * 4u) + threadIdx.x;

    // Front-batch 4 independent loads -> MLP=4.
    float4 v0 = in[base + 0u * T];
    float4 v1 = in[base + 1u * T];
    float4 v2 = in[base + 2u * T];
    float4 v3 = in[base + 3u * T];

    out[base + 0u * T] = f4(v0);
    out[base + 1u * T] = f4(v1);
    out[base + 2u * T] = f4(v2);
    out[base + 3u * T] = f4(v3);
}

extern "C" void kernel_launch(void* const* d_in, const int* in_sizes, int n_in,
                              void* d_out, int out_size) {
    const float4* in = (const float4*)d_in[0];
    float4* out = (float4*)d_out;
    int n = in_sizes[0];             // 67108864
    int n4 = n / 4;                  // 16777216 float4s
    int blocks = n4 / (1024 * 4);    // 4096, exact
    elemwise_kernel<<<blocks, 1024>>>(in, out);
}

// round 17
// speedup vs baseline: 1.0023x; 1.0023x over previous
#include <cuda_runtime.h>

// y = min(((x + 1) * 0.75)^2, 10)  — elementwise over 8192*8192 fp32.
// FINAL — roofline kernel, verified across 8 reproductions
// (wall 81.98-82.21us, ncu 73.7-74.9us, DRAM 80.9-82.5%, ~6.4-6.5 TB/s).
//
// HBM-bound at the sustained power-limited roofline: 512MB irreducible
// traffic / ~6.45 TB/s sustained ≈ 80us floor + ~1.5us replay overhead.
//
// Complete isolated lever sweep (16 rounds):
//  - per-thread MLP: saturates at 4 front-batched float4 loads
//    (the only real win: DRAM 77.8% -> 82%); MLP=8 regresses occupancy
//  - block size 256/512/1024: statistical tie (1024 chosen)
//  - 128-bit vs 256-bit (v8.f32) accesses: tie
//  - cache hints (__ldcs/__stcs): neutral (de-confounded)
//  - persistent grid / interleaved ld-st batches: regress
//  - coalesced blockDim-stride addressing, exact grid, no bounds checks:
//    67108864 = 4096 blocks * 1024 thr * 16 elems

#define T 1024u

__device__ __forceinline__ float f(float x) {
    float t = (x + 1.0f) * 0.75f;
    float y = t * t;
    return fminf(y, 10.0f);
}

__device__ __forceinline__ float4 f4(float4 v) {
    float4 r;
    r.x = f(v.x); r.y = f(v.y); r.z = f(v.z); r.w = f(v.w);
    return r;
}

__global__ __launch_bounds__(1024) void elemwise_kernel(const float4* __restrict__ in,
                                                        float4* __restrict__ out) {
    unsigned base = blockIdx.x * (T * 4u) + threadIdx.x;

    // Front-batch 4 independent loads -> MLP=4.
    float4 v0 = in[base + 0u * T];
    float4 v1 = in[base + 1u * T];
    float4 v2 = in[base + 2u * T];
    float4 v3 = in[base + 3u * T];

    out[base + 0u * T] = f4(v0);
    out[base + 1u * T] = f4(v1);
    out[base + 2u * T] = f4(v2);
    out[base + 3u * T] = f4(v3);
}

extern "C" void kernel_launch(void* const* d_in, const int* in_sizes, int n_in,
                              void* d_out, int out_size) {
    const float4* in = (const float4*)d_in[0];
    float4* out = (float4*)d_out;
    int n = in_sizes[0];             // 67108864
    int n4 = n / 4;                  // 16777216 float4s
    int blocks = n4 / (1024 * 4);    // 4096, exact
    elemwise_kernel<<<blocks, 1024>>>(in, out);
}